// round 15
// baseline (speedup 1.0000x reference)
#include <cuda_runtime.h>
#include <cuda_bf16.h>
#include <cstdint>

// ---------------------------------------------------------------------------
// GraphSAGE forward on GB300 — bf16 activations + bf16 weights (1-pass
// mma.sync GEMMs), 2-edge-wide CSR mean aggregation, bf16 residual.
// ---------------------------------------------------------------------------
namespace {
constexpr int Nn = 100000;   // nodes
constexpr int Ee = 1600000;  // edges
constexpr int Hc = 128;      // hidden channels
constexpr int Oc = 64;       // out channels
constexpr int NP = 100096;   // padded rows (multiple of 128)
constexpr int NT = NP / 128; // 782 CTA tiles
// weight scratch layout (combined [Wl|Wr] per layer, row-major [n][k])
constexpr int WOFF_IN = 0;
constexpr int WOFF_H = 16384;
constexpr int WOFF_O = 16384 + 3 * 32768;
constexpr int WTOT = WOFF_O + 64 * 256;  // 131072
}

// ------------------------- static device scratch ---------------------------
__device__ __align__(16) __nv_bfloat16 g_inp[(size_t)NP * Hc]; // pre-relu inProj (bf16)
__device__ __align__(16) __nv_bfloat16 g_x[(size_t)NP * Hc];   // x bf16
__device__ __align__(16) __nv_bfloat16 g_h0[(size_t)NP * Hc];  // h ping
__device__ __align__(16) __nv_bfloat16 g_h1[(size_t)NP * Hc];  // h pong
__device__ __align__(16) __nv_bfloat16 g_m[(size_t)NP * Hc];   // mean
__device__ float g_invdeg[Nn];
__device__ int   g_cnt[Nn];
__device__ int   g_rowptr[Nn + 1];
__device__ int   g_cursor[Nn];
__device__ int   g_csr[Ee];
__device__ __align__(16) __nv_bfloat16 g_Bw[WTOT];

// ------------------------------ PTX helpers --------------------------------
__device__ __forceinline__ uint32_t smem_to_u32(const void* p) {
    uint32_t a;
    asm("{ .reg .u64 t; cvta.to.shared.u64 t, %1; cvt.u32.u64 %0, t; }"
        : "=r"(a) : "l"(p));
    return a;
}
__device__ __forceinline__ void ldsm_x4(uint32_t* r, uint32_t addr) {
    asm volatile("ldmatrix.sync.aligned.m8n8.x4.shared.b16 {%0,%1,%2,%3}, [%4];"
                 : "=r"(r[0]), "=r"(r[1]), "=r"(r[2]), "=r"(r[3]) : "r"(addr));
}
__device__ __forceinline__ void mma_bf16(float* c, const uint32_t* a, const uint32_t* b) {
    asm volatile(
        "mma.sync.aligned.m16n8k16.row.col.f32.bf16.bf16.f32 "
        "{%0,%1,%2,%3}, {%4,%5,%6,%7}, {%8,%9}, {%0,%1,%2,%3};"
        : "+f"(c[0]), "+f"(c[1]), "+f"(c[2]), "+f"(c[3])
        : "r"(a[0]), "r"(a[1]), "r"(a[2]), "r"(a[3]), "r"(b[0]), "r"(b[1]));
}
__device__ __forceinline__ void cp16(uint32_t saddr, const void* g) {
    asm volatile("cp.async.cg.shared.global [%0], [%1], 16;"
                 :: "r"(saddr), "l"(g) : "memory");
}
#define CP_COMMIT() asm volatile("cp.async.commit_group;" ::: "memory")
#define CP_WAIT0()  asm volatile("cp.async.wait_group 0;" ::: "memory")

__device__ __forceinline__ uint32_t pack_bf2(float a, float b) {
    __nv_bfloat162 v = __floats2bfloat162_rn(a, b);
    return *reinterpret_cast<uint32_t*>(&v);
}
__device__ __forceinline__ float2 bf2_to_f2(uint32_t u) {
    __nv_bfloat162 b = *reinterpret_cast<__nv_bfloat162*>(&u);
    return __bfloat1622float2(b);
}

// ----------------------------- CSR construction ----------------------------
__global__ void k_zero_cnt() {
    int i = blockIdx.x * blockDim.x + threadIdx.x;
    if (i < Nn) g_cnt[i] = 0;
}
__global__ void k_hist(const int* __restrict__ dst) {
    int i = blockIdx.x * blockDim.x + threadIdx.x;
    if (i < Ee) atomicAdd(&g_cnt[dst[i]], 1);
}
__global__ void k_scan() {
    __shared__ int sums[1024];
    const int t = threadIdx.x;
    const int CH = 128;
    const int base = t * CH;
    int s = 0;
    for (int i = 0; i < CH; i++) {
        int idx = base + i;
        if (idx < Nn) s += g_cnt[idx];
    }
    sums[t] = s;
    __syncthreads();
    int mine = s;
    for (int d = 1; d < 1024; d <<= 1) {
        int v = (t >= d) ? sums[t - d] : 0;
        __syncthreads();
        sums[t] += v;
        __syncthreads();
    }
    int run = sums[t] - mine;
    for (int i = 0; i < CH; i++) {
        int idx = base + i;
        if (idx < Nn) {
            int c = g_cnt[idx];
            g_rowptr[idx] = run;
            g_cursor[idx] = run;
            g_invdeg[idx] = 1.0f / fmaxf((float)c, 1.0f);
            run += c;
        }
    }
    if (t == 0) g_rowptr[Nn] = Ee;
}
__global__ void k_fill(const int* __restrict__ src, const int* __restrict__ dst) {
    int i = blockIdx.x * blockDim.x + threadIdx.x;
    if (i < Ee) {
        int d = dst[i];
        int pos = atomicAdd(&g_cursor[d], 1);
        g_csr[pos] = src[i];
    }
}

// ---- mean aggregation (warp / node, 16 lanes per row, 2 edges / inst) -----
// Lane l: edge slot e2 = l>>4, 16B chunk c = l&15 (bf16 cols c*8..c*8+7).
// 8x LDG.128 puts 16 edges in flight; shfl_xor(16) merges the two slots.
__global__ __launch_bounds__(256) void k_agg(const __nv_bfloat16* __restrict__ h) {
    int warp = (blockIdx.x * blockDim.x + threadIdx.x) >> 5;
    if (warp >= Nn) return;
    const int lane = threadIdx.x & 31;
    const int e2 = lane >> 4;
    const int c = lane & 15;
    const char* base = (const char*)h;
    const uint32_t loff = (uint32_t)(c * 16);
    int b = g_rowptr[warp];
    int e = g_rowptr[warp + 1];
    float a0 = 0.f, a1 = 0.f, a2 = 0.f, a3 = 0.f;
    float a4 = 0.f, a5 = 0.f, a6 = 0.f, a7 = 0.f;
    for (int i = b; i < e; i += 16) {
        const int cnt = min(16, e - i);
        int cv = 0;
        if (lane < cnt) cv = g_csr[i + lane];
#pragma unroll
        for (int j = 0; j < 8; j++) {
            const int idx = j * 2 + e2;
            const int srow = __shfl_sync(0xFFFFFFFFu, cv, idx);
            if (idx < cnt) {
                uint4 u = *(const uint4*)(base + (size_t)srow * 256 + loff);
                float2 f;
                f = bf2_to_f2(u.x); a0 += f.x; a1 += f.y;
                f = bf2_to_f2(u.y); a2 += f.x; a3 += f.y;
                f = bf2_to_f2(u.z); a4 += f.x; a5 += f.y;
                f = bf2_to_f2(u.w); a6 += f.x; a7 += f.y;
            }
        }
    }
    a0 += __shfl_xor_sync(0xFFFFFFFFu, a0, 16);
    a1 += __shfl_xor_sync(0xFFFFFFFFu, a1, 16);
    a2 += __shfl_xor_sync(0xFFFFFFFFu, a2, 16);
    a3 += __shfl_xor_sync(0xFFFFFFFFu, a3, 16);
    a4 += __shfl_xor_sync(0xFFFFFFFFu, a4, 16);
    a5 += __shfl_xor_sync(0xFFFFFFFFu, a5, 16);
    a6 += __shfl_xor_sync(0xFFFFFFFFu, a6, 16);
    a7 += __shfl_xor_sync(0xFFFFFFFFu, a7, 16);
    if (e2 == 0) {
        float id = g_invdeg[warp];
        uint4 o;
        o.x = pack_bf2(a0 * id, a1 * id);
        o.y = pack_bf2(a2 * id, a3 * id);
        o.z = pack_bf2(a4 * id, a5 * id);
        o.w = pack_bf2(a6 * id, a7 * id);
        *(uint4*)((char*)g_m + (size_t)warp * 256 + loff) = o;
    }
}

// ------------------------ conversions (weights, x) --------------------------
__global__ void k_wconv(const float* __restrict__ Wp, const float* __restrict__ Wl_h,
                        const float* __restrict__ Wr_h, const float* __restrict__ Wl_o,
                        const float* __restrict__ Wr_o) {
    int i = blockIdx.x * blockDim.x + threadIdx.x;
    if (i >= WTOT) return;
    float w;
    if (i < WOFF_H) {
        w = Wp[i];
    } else if (i < WOFF_O) {
        int j = i - WOFF_H;
        int layer = j / 32768;
        int r = j % 32768;
        int n = r >> 8, k = r & 255;
        w = (k < 128) ? Wl_h[layer * 16384 + n * 128 + k]
                      : Wr_h[layer * 16384 + n * 128 + (k - 128)];
    } else {
        int r = i - WOFF_O;
        int n = r >> 8, k = r & 255;
        w = (k < 128) ? Wl_o[n * 128 + k] : Wr_o[n * 128 + (k - 128)];
    }
    g_Bw[i] = __float2bfloat16(w);
}

__global__ void k_xconv(const float* __restrict__ x) {
    int i = blockIdx.x * blockDim.x + threadIdx.x;
    if (i >= Nn * 32) return;
    const float4 f = ((const float4*)x)[i];
    ((uint2*)g_x)[i] = make_uint2(pack_bf2(f.x, f.y), pack_bf2(f.z, f.w));
}

// --------------------- smem-fed mma.sync 1-pass GEMM -----------------------
// CTA m128 x nNOUT, 512 threads = 16 warps (8m x 2n), warp m16 x n(NOUT/2).
// A: bf16 activations (256B/row) staged via cp.async, pitch 272.
// B: bf16 weights staged per phase, pitch 272. D = A*B.
template <int NOUT, int NPH, bool RELU, bool RESID, bool PRE, bool WM, bool WPK>
__global__ __launch_bounds__(512) void k_mgemm(
    const __nv_bfloat16* __restrict__ A0, const __nv_bfloat16* __restrict__ A1,
    const __nv_bfloat16* __restrict__ Bw,
    const float* __restrict__ bias, const __nv_bfloat16* __restrict__ resid,
    float* __restrict__ outm, __nv_bfloat16* __restrict__ outp,
    __nv_bfloat16* __restrict__ outb) {
    extern __shared__ char smem[];
    constexpr int ASZ = 128 * 272;           // A plane per phase (pitch 272B)
    constexpr int OFF_B = NPH * ASZ;
    constexpr int BPL = NOUT * 272;          // B plane (pitch 272B)
    constexpr int OFF_BIAS = OFF_B + BPL;
    constexpr int KTOT = NPH * 128;
    constexpr int NI = NOUT / 16;            // n8 tiles per warp (8 or 4)
    constexpr int NW = NI * 8;               // warp n width

    const uint32_t sm32 = smem_to_u32(smem);
    const int tid = threadIdx.x;
    const int lane = tid & 31;
    const int wid = tid >> 5;
    const int wm = wid & 7;                  // m block (16 rows)
    const int wn = wid >> 3;                 // n block (NW cols)
    const int m0 = blockIdx.x * 128;

    // ---- stage all A phases + B phase 0 ----
#pragma unroll
    for (int p = 0; p < NPH; p++) {
        const __nv_bfloat16* Ap = (p ? A1 : A0) + (size_t)m0 * 128;
        for (int idx = tid; idx < 2048; idx += 512) {
            int r = idx >> 4, g = idx & 15;
            cp16(sm32 + p * ASZ + r * 272 + g * 16, Ap + (size_t)r * 128 + g * 8);
        }
    }
    for (int g = tid; g < NOUT * 16; g += 512) {
        int n = g >> 4, c = g & 15;
        cp16(sm32 + OFF_B + n * 272 + c * 16, Bw + (size_t)n * KTOT + c * 8);
    }
    CP_COMMIT();
    if (tid < NOUT) *(float*)(smem + OFF_BIAS + tid * 4) = bias[tid];
    CP_WAIT0();
    __syncthreads();

    const int r8 = lane & 7, q = lane >> 3;
    const uint32_t aoff =
        (uint32_t)((wm * 16 + (q & 1) * 8 + r8) * 272 + (q >> 1) * 16);
    const uint32_t boff =
        (uint32_t)((wn * NW + (q >> 1) * 8 + r8) * 272 + (q & 1) * 16);
    const uint32_t bBase = sm32 + OFF_B + boff;

    float acc[NI][4];
#pragma unroll
    for (int ni = 0; ni < NI; ni++)
#pragma unroll
        for (int c = 0; c < 4; c++) acc[ni][c] = 0.f;

#pragma unroll
    for (int p = 0; p < NPH; p++) {
        if (p > 0) {
            __syncthreads();
            for (int g = tid; g < NOUT * 16; g += 512) {
                int n = g >> 4, c = g & 15;
                cp16(sm32 + OFF_B + n * 272 + c * 16,
                     Bw + (size_t)n * KTOT + p * 128 + c * 8);
            }
            CP_COMMIT();
            CP_WAIT0();
            __syncthreads();
        }
        const uint32_t aBase = sm32 + (uint32_t)(p * ASZ) + aoff;
#pragma unroll
        for (int kb = 0; kb < 8; kb++) {
            uint32_t a[4];
            ldsm_x4(a, aBase + kb * 32);
            uint32_t bf[NI / 2][4];
#pragma unroll
            for (int nt = 0; nt < NI / 2; nt++)
                ldsm_x4(bf[nt], bBase + nt * 16 * 272 + kb * 32);
#pragma unroll
            for (int ni = 0; ni < NI; ni++)
                mma_bf16(acc[ni], a, &bf[ni >> 1][(ni & 1) * 2]);
        }
    }

    // ------------------------------ epilogue -------------------------------
    const float* biasS = (const float*)(smem + OFF_BIAS);
    const int q4 = lane & 3;
    const int rbase = m0 + wm * 16 + (lane >> 2);
#pragma unroll
    for (int ni = 0; ni < NI; ni++) {
        const int col = wn * NW + ni * 8 + q4 * 2;
        const float b0 = biasS[col], b1 = biasS[col + 1];
#pragma unroll
        for (int half = 0; half < 2; half++) {
            const int row = rbase + half * 8;
            float x0 = acc[ni][half * 2 + 0] + b0;
            float x1 = acc[ni][half * 2 + 1] + b1;
            if (PRE)
                *(uint32_t*)((char*)outp + (size_t)row * 256 + col * 2) = pack_bf2(x0, x1);
            if (RELU) { x0 = fmaxf(x0, 0.f); x1 = fmaxf(x1, 0.f); }
            if (RESID) {
                uint32_t ru = *(const uint32_t*)((const char*)resid + (size_t)row * 256 + col * 2);
                float2 rr = bf2_to_f2(ru);
                x0 = fmaf(0.2f, rr.x, x0);
                x1 = fmaf(0.2f, rr.y, x1);
            }
            if (WM) {
                if (row < Nn)
                    *(float2*)(outm + (size_t)row * NOUT + col) = make_float2(x0, x1);
            }
            if (WPK)
                *(uint32_t*)((char*)outb + (size_t)row * 256 + col * 2) = pack_bf2(x0, x1);
        }
    }
}

// ------------------------------ log-softmax --------------------------------
__global__ __launch_bounds__(256) void k_lsm(float* __restrict__ out) {
    int warp = (blockIdx.x * blockDim.x + threadIdx.x) >> 5;
    if (warp >= Nn) return;
    int lane = threadIdx.x & 31;
    float2 v = *(float2*)(out + (size_t)warp * Oc + lane * 2);
    float m = fmaxf(v.x, v.y);
#pragma unroll
    for (int o = 16; o; o >>= 1) m = fmaxf(m, __shfl_xor_sync(0xFFFFFFFFu, m, o));
    float s = expf(v.x - m) + expf(v.y - m);
#pragma unroll
    for (int o = 16; o; o >>= 1) s += __shfl_xor_sync(0xFFFFFFFFu, s, o);
    float l = m + logf(s);
    v.x -= l;
    v.y -= l;
    *(float2*)(out + (size_t)warp * Oc + lane * 2) = v;
}

// ------------------------------- launcher ----------------------------------
extern "C" void kernel_launch(void* const* d_in, const int* in_sizes, int n_in,
                              void* d_out, int out_size) {
    const float* x    = (const float*)d_in[0];
    const int*   ei   = (const int*)d_in[1];
    const float* Wp   = (const float*)d_in[2];
    const float* bp   = (const float*)d_in[3];
    const float* Wl_h = (const float*)d_in[4];
    const float* bl_h = (const float*)d_in[5];
    const float* Wr_h = (const float*)d_in[6];
    const float* Wl_o = (const float*)d_in[7];
    const float* bl_o = (const float*)d_in[8];
    const float* Wr_o = (const float*)d_in[9];
    const int* src = ei;
    const int* dst = ei + Ee;
    float* out = (float*)d_out;

    __nv_bfloat16 *p_inp, *p_x, *p_h0, *p_h1, *p_m, *p_bw;
    cudaGetSymbolAddress((void**)&p_inp, g_inp);
    cudaGetSymbolAddress((void**)&p_x, g_x);
    cudaGetSymbolAddress((void**)&p_h0, g_h0);
    cudaGetSymbolAddress((void**)&p_h1, g_h1);
    cudaGetSymbolAddress((void**)&p_m, g_m);
    cudaGetSymbolAddress((void**)&p_bw, g_Bw);

    auto gemm_in  = k_mgemm<128, 1, true, false, true, false, true>;
    auto gemm_hid = k_mgemm<128, 2, true, true, false, false, true>;
    auto gemm_out = k_mgemm<64, 2, false, false, false, true, false>;
    const int SM_IN  = 1 * 128 * 272 + 128 * 272 + 512;  // 70144
    const int SM_HID = 2 * 128 * 272 + 128 * 272 + 512;  // 104960
    const int SM_OUT = 2 * 128 * 272 + 64 * 272 + 256;   // 87296
    cudaFuncSetAttribute(gemm_in, cudaFuncAttributeMaxDynamicSharedMemorySize, SM_IN);
    cudaFuncSetAttribute(gemm_hid, cudaFuncAttributeMaxDynamicSharedMemorySize, SM_HID);
    cudaFuncSetAttribute(gemm_out, cudaFuncAttributeMaxDynamicSharedMemorySize, SM_OUT);

    // Launch order: ncu captures launch index 3 -> gemm_in.
    k_wconv<<<(WTOT + 255) / 256, 256>>>(Wp, Wl_h, Wr_h, Wl_o, Wr_o);          // 0
    k_xconv<<<(Nn * 32 + 255) / 256, 256>>>(x);                                // 1
    k_zero_cnt<<<(Nn + 255) / 256, 256>>>();                                   // 2
    gemm_in<<<NT, 512, SM_IN>>>(p_x, nullptr, p_bw + WOFF_IN,                  // 3
                                bp, nullptr, nullptr, p_inp, p_h0);
    k_hist<<<(Ee + 255) / 256, 256>>>(dst);                                    // 4
    k_scan<<<1, 1024>>>();                                                     // 5
    k_fill<<<(Ee + 255) / 256, 256>>>(src, dst);                               // 6

    const int ga = ((Nn * 32) + 255) / 256;

    __nv_bfloat16 *h = p_h0, *nh = p_h1;
    for (int i = 0; i < 3; i++) {
        k_agg<<<ga, 256>>>(h);
        gemm_hid<<<NT, 512, SM_HID>>>(p_m, h, p_bw + WOFF_H + i * 32768,
                                      bl_h + (size_t)i * 128, p_inp,
                                      nullptr, nullptr, nh);
        __nv_bfloat16* t = h; h = nh; nh = t;
    }

    k_agg<<<ga, 256>>>(h);
    gemm_out<<<NT, 512, SM_OUT>>>(p_m, h, p_bw + WOFF_O,
                                  bl_o, nullptr, out, nullptr, nullptr);
    k_lsm<<<ga, 256>>>(out);
}

// round 16
// speedup vs baseline: 1.0452x; 1.0452x over previous
#include <cuda_runtime.h>
#include <cuda_bf16.h>
#include <cstdint>

// ---------------------------------------------------------------------------
// GraphSAGE forward on GB300 — bf16 activations + bf16 weights (1-pass
// mma.sync GEMMs), 16-deep CSR mean aggregation, fused log-softmax epilogue.
// ---------------------------------------------------------------------------
namespace {
constexpr int Nn = 100000;   // nodes
constexpr int Ee = 1600000;  // edges
constexpr int Hc = 128;      // hidden channels
constexpr int Oc = 64;       // out channels
constexpr int NP = 100096;   // padded rows (multiple of 128)
constexpr int NT = NP / 128; // 782 CTA tiles
// weight scratch layout (combined [Wl|Wr] per layer, row-major [n][k])
constexpr int WOFF_IN = 0;
constexpr int WOFF_H = 16384;
constexpr int WOFF_O = 16384 + 3 * 32768;
constexpr int WTOT = WOFF_O + 64 * 256;  // 131072
}

// ------------------------- static device scratch ---------------------------
__device__ float g_inp[(size_t)NP * Hc];                       // pre-relu inProj
__device__ __align__(16) __nv_bfloat16 g_x[(size_t)NP * Hc];   // x bf16
__device__ __align__(16) __nv_bfloat16 g_h0[(size_t)NP * Hc];  // h ping
__device__ __align__(16) __nv_bfloat16 g_h1[(size_t)NP * Hc];  // h pong
__device__ __align__(16) __nv_bfloat16 g_m[(size_t)NP * Hc];   // mean
__device__ float g_invdeg[Nn];
__device__ int   g_cnt[Nn];
__device__ int   g_rowptr[Nn + 1];
__device__ int   g_cursor[Nn];
__device__ int   g_csr[Ee];
__device__ __align__(16) __nv_bfloat16 g_Bw[WTOT];

// ------------------------------ PTX helpers --------------------------------
__device__ __forceinline__ uint32_t smem_to_u32(const void* p) {
    uint32_t a;
    asm("{ .reg .u64 t; cvta.to.shared.u64 t, %1; cvt.u32.u64 %0, t; }"
        : "=r"(a) : "l"(p));
    return a;
}
__device__ __forceinline__ void ldsm_x4(uint32_t* r, uint32_t addr) {
    asm volatile("ldmatrix.sync.aligned.m8n8.x4.shared.b16 {%0,%1,%2,%3}, [%4];"
                 : "=r"(r[0]), "=r"(r[1]), "=r"(r[2]), "=r"(r[3]) : "r"(addr));
}
__device__ __forceinline__ void mma_bf16(float* c, const uint32_t* a, const uint32_t* b) {
    asm volatile(
        "mma.sync.aligned.m16n8k16.row.col.f32.bf16.bf16.f32 "
        "{%0,%1,%2,%3}, {%4,%5,%6,%7}, {%8,%9}, {%0,%1,%2,%3};"
        : "+f"(c[0]), "+f"(c[1]), "+f"(c[2]), "+f"(c[3])
        : "r"(a[0]), "r"(a[1]), "r"(a[2]), "r"(a[3]), "r"(b[0]), "r"(b[1]));
}
__device__ __forceinline__ void cp16(uint32_t saddr, const void* g) {
    asm volatile("cp.async.cg.shared.global [%0], [%1], 16;"
                 :: "r"(saddr), "l"(g) : "memory");
}
#define CP_COMMIT() asm volatile("cp.async.commit_group;" ::: "memory")
#define CP_WAIT0()  asm volatile("cp.async.wait_group 0;" ::: "memory")

__device__ __forceinline__ uint32_t pack_bf2(float a, float b) {
    __nv_bfloat162 v = __floats2bfloat162_rn(a, b);
    return *reinterpret_cast<uint32_t*>(&v);
}
__device__ __forceinline__ float2 bf2_to_f2(uint32_t u) {
    __nv_bfloat162 b = *reinterpret_cast<__nv_bfloat162*>(&u);
    return __bfloat1622float2(b);
}

// ----------------------------- CSR construction ----------------------------
__global__ void k_zero_cnt() {
    int i = blockIdx.x * blockDim.x + threadIdx.x;
    if (i < Nn) g_cnt[i] = 0;
}
__global__ void k_hist(const int* __restrict__ dst) {
    int i = blockIdx.x * blockDim.x + threadIdx.x;
    if (i < Ee) atomicAdd(&g_cnt[dst[i]], 1);
}
__global__ void k_scan() {
    __shared__ int sums[1024];
    const int t = threadIdx.x;
    const int CH = 128;
    const int base = t * CH;
    int s = 0;
    for (int i = 0; i < CH; i++) {
        int idx = base + i;
        if (idx < Nn) s += g_cnt[idx];
    }
    sums[t] = s;
    __syncthreads();
    int mine = s;
    for (int d = 1; d < 1024; d <<= 1) {
        int v = (t >= d) ? sums[t - d] : 0;
        __syncthreads();
        sums[t] += v;
        __syncthreads();
    }
    int run = sums[t] - mine;
    for (int i = 0; i < CH; i++) {
        int idx = base + i;
        if (idx < Nn) {
            int c = g_cnt[idx];
            g_rowptr[idx] = run;
            g_cursor[idx] = run;
            g_invdeg[idx] = 1.0f / fmaxf((float)c, 1.0f);
            run += c;
        }
    }
    if (t == 0) g_rowptr[Nn] = Ee;
}
__global__ void k_fill(const int* __restrict__ src, const int* __restrict__ dst) {
    int i = blockIdx.x * blockDim.x + threadIdx.x;
    if (i < Ee) {
        int d = dst[i];
        int pos = atomicAdd(&g_cursor[d], 1);
        g_csr[pos] = src[i];
    }
}

// ------ mean aggregation (warp / node, contiguous bf16 rows, 256B/edge) ----
__global__ __launch_bounds__(256) void k_agg(const __nv_bfloat16* __restrict__ h) {
    int warp = (blockIdx.x * blockDim.x + threadIdx.x) >> 5;
    if (warp >= Nn) return;
    int lane = threadIdx.x & 31;
    const char* base = (const char*)h;
    const uint32_t loff = (uint32_t)(lane * 8);
    int b = g_rowptr[warp];
    int e = g_rowptr[warp + 1];
    float a0 = 0.f, a1 = 0.f, a2 = 0.f, a3 = 0.f;
    int i = b;
    for (; i + 15 < e; i += 16) {
        uint2 u[16];
#pragma unroll
        for (int j = 0; j < 16; j++)
            u[j] = *(const uint2*)(base + (size_t)g_csr[i + j] * 256 + loff);
#pragma unroll
        for (int j = 0; j < 16; j++) {
            float2 f;
            f = bf2_to_f2(u[j].x); a0 += f.x; a1 += f.y;
            f = bf2_to_f2(u[j].y); a2 += f.x; a3 += f.y;
        }
    }
    if (i + 7 < e) {
        uint2 u[8];
#pragma unroll
        for (int j = 0; j < 8; j++)
            u[j] = *(const uint2*)(base + (size_t)g_csr[i + j] * 256 + loff);
#pragma unroll
        for (int j = 0; j < 8; j++) {
            float2 f;
            f = bf2_to_f2(u[j].x); a0 += f.x; a1 += f.y;
            f = bf2_to_f2(u[j].y); a2 += f.x; a3 += f.y;
        }
        i += 8;
    }
    for (; i < e; i++) {
        uint2 u0 = *(const uint2*)(base + (size_t)g_csr[i] * 256 + loff);
        float2 f;
        f = bf2_to_f2(u0.x); a0 += f.x; a1 += f.y;
        f = bf2_to_f2(u0.y); a2 += f.x; a3 += f.y;
    }
    float id = g_invdeg[warp];
    a0 *= id; a1 *= id; a2 *= id; a3 *= id;
    *(uint2*)((char*)g_m + (size_t)warp * 256 + loff) =
        make_uint2(pack_bf2(a0, a1), pack_bf2(a2, a3));
}

// ------------------------ conversions (weights, x) --------------------------
__global__ void k_wconv(const float* __restrict__ Wp, const float* __restrict__ Wl_h,
                        const float* __restrict__ Wr_h, const float* __restrict__ Wl_o,
                        const float* __restrict__ Wr_o) {
    int i = blockIdx.x * blockDim.x + threadIdx.x;
    if (i >= WTOT) return;
    float w;
    if (i < WOFF_H) {
        w = Wp[i];
    } else if (i < WOFF_O) {
        int j = i - WOFF_H;
        int layer = j / 32768;
        int r = j % 32768;
        int n = r >> 8, k = r & 255;
        w = (k < 128) ? Wl_h[layer * 16384 + n * 128 + k]
                      : Wr_h[layer * 16384 + n * 128 + (k - 128)];
    } else {
        int r = i - WOFF_O;
        int n = r >> 8, k = r & 255;
        w = (k < 128) ? Wl_o[n * 128 + k] : Wr_o[n * 128 + (k - 128)];
    }
    g_Bw[i] = __float2bfloat16(w);
}

__global__ void k_xconv(const float* __restrict__ x) {
    int i = blockIdx.x * blockDim.x + threadIdx.x;
    if (i >= Nn * 32) return;
    const float4 f = ((const float4*)x)[i];
    ((uint2*)g_x)[i] = make_uint2(pack_bf2(f.x, f.y), pack_bf2(f.z, f.w));
}

// --------------------- smem-fed mma.sync 1-pass GEMM -----------------------
// CTA m128 x nNOUT, 512 threads = 16 warps (8m x 2n), warp m16 x n(NOUT/2).
// A: bf16 activations (256B/row) staged via cp.async, pitch 272.
// B: bf16 weights staged per phase, pitch 272. D = A*B.
// LSM: fused log-softmax over NOUT=64 columns, written to outm.
template <int NOUT, int NPH, bool RELU, bool RESID, bool PRE, bool WM, bool WPK, bool LSM>
__global__ __launch_bounds__(512) void k_mgemm(
    const __nv_bfloat16* __restrict__ A0, const __nv_bfloat16* __restrict__ A1,
    const __nv_bfloat16* __restrict__ Bw,
    const float* __restrict__ bias, const float* __restrict__ resid,
    float* __restrict__ outm, float* __restrict__ outp,
    __nv_bfloat16* __restrict__ outb) {
    extern __shared__ char smem[];
    constexpr int ASZ = 128 * 272;           // A plane per phase (pitch 272B)
    constexpr int OFF_B = NPH * ASZ;
    constexpr int BPL = NOUT * 272;          // B plane (pitch 272B)
    constexpr int OFF_BIAS = OFF_B + BPL;
    constexpr int KTOT = NPH * 128;
    constexpr int NI = NOUT / 16;            // n8 tiles per warp (8 or 4)
    constexpr int NW = NI * 8;               // warp n width

    const uint32_t sm32 = smem_to_u32(smem);
    const int tid = threadIdx.x;
    const int lane = tid & 31;
    const int wid = tid >> 5;
    const int wm = wid & 7;                  // m block (16 rows)
    const int wn = wid >> 3;                 // n block (NW cols)
    const int m0 = blockIdx.x * 128;

    // ---- stage all A phases + B phase 0 ----
#pragma unroll
    for (int p = 0; p < NPH; p++) {
        const __nv_bfloat16* Ap = (p ? A1 : A0) + (size_t)m0 * 128;
        for (int idx = tid; idx < 2048; idx += 512) {
            int r = idx >> 4, g = idx & 15;
            cp16(sm32 + p * ASZ + r * 272 + g * 16, Ap + (size_t)r * 128 + g * 8);
        }
    }
    for (int g = tid; g < NOUT * 16; g += 512) {
        int n = g >> 4, c = g & 15;
        cp16(sm32 + OFF_B + n * 272 + c * 16, Bw + (size_t)n * KTOT + c * 8);
    }
    CP_COMMIT();
    if (tid < NOUT) *(float*)(smem + OFF_BIAS + tid * 4) = bias[tid];
    CP_WAIT0();
    __syncthreads();

    const int r8 = lane & 7, q = lane >> 3;
    const uint32_t aoff =
        (uint32_t)((wm * 16 + (q & 1) * 8 + r8) * 272 + (q >> 1) * 16);
    const uint32_t boff =
        (uint32_t)((wn * NW + (q >> 1) * 8 + r8) * 272 + (q & 1) * 16);
    const uint32_t bBase = sm32 + OFF_B + boff;

    float acc[NI][4];
#pragma unroll
    for (int ni = 0; ni < NI; ni++)
#pragma unroll
        for (int c = 0; c < 4; c++) acc[ni][c] = 0.f;

#pragma unroll
    for (int p = 0; p < NPH; p++) {
        if (p > 0) {
            __syncthreads();
            for (int g = tid; g < NOUT * 16; g += 512) {
                int n = g >> 4, c = g & 15;
                cp16(sm32 + OFF_B + n * 272 + c * 16,
                     Bw + (size_t)n * KTOT + p * 128 + c * 8);
            }
            CP_COMMIT();
            CP_WAIT0();
            __syncthreads();
        }
        const uint32_t aBase = sm32 + (uint32_t)(p * ASZ) + aoff;
#pragma unroll
        for (int kb = 0; kb < 8; kb++) {
            uint32_t a[4];
            ldsm_x4(a, aBase + kb * 32);
            uint32_t bf[NI / 2][4];
#pragma unroll
            for (int nt = 0; nt < NI / 2; nt++)
                ldsm_x4(bf[nt], bBase + nt * 16 * 272 + kb * 32);
#pragma unroll
            for (int ni = 0; ni < NI; ni++)
                mma_bf16(acc[ni], a, &bf[ni >> 1][(ni & 1) * 2]);
        }
    }

    if (LSM) __syncthreads();  // A smem no longer needed; reuse as fp32 buffer
    float* lsmbuf = (float*)smem;

    // ------------------------------ epilogue -------------------------------
    const float* biasS = (const float*)(smem + OFF_BIAS);
    const int q4 = lane & 3;
    const int rbase = m0 + wm * 16 + (lane >> 2);
#pragma unroll
    for (int ni = 0; ni < NI; ni++) {
        const int col = wn * NW + ni * 8 + q4 * 2;
        const float b0 = biasS[col], b1 = biasS[col + 1];
#pragma unroll
        for (int half = 0; half < 2; half++) {
            const int row = rbase + half * 8;
            float x0 = acc[ni][half * 2 + 0] + b0;
            float x1 = acc[ni][half * 2 + 1] + b1;
            if (PRE) *(float2*)(outp + (size_t)row * 128 + col) = make_float2(x0, x1);
            if (RELU) { x0 = fmaxf(x0, 0.f); x1 = fmaxf(x1, 0.f); }
            if (RESID) {
                float2 rr = *(const float2*)(resid + (size_t)row * 128 + col);
                x0 = fmaf(0.2f, rr.x, x0);
                x1 = fmaf(0.2f, rr.y, x1);
            }
            if (WM) {
                if (row < Nn)
                    *(float2*)(outm + (size_t)row * NOUT + col) = make_float2(x0, x1);
            }
            if (WPK)
                *(uint32_t*)((char*)outb + (size_t)row * 256 + col * 2) = pack_bf2(x0, x1);
            if (LSM) {
                lsmbuf[(row - m0) * NOUT + col] = x0;
                lsmbuf[(row - m0) * NOUT + col + 1] = x1;
            }
        }
    }

    if (LSM) {
        __syncthreads();
        // each warp handles 8 rows; lane covers 2 columns of NOUT=64
#pragma unroll
        for (int rr = 0; rr < 8; rr++) {
            const int lr = wid * 8 + rr;
            const int row = m0 + lr;
            float v0 = lsmbuf[lr * NOUT + lane * 2];
            float v1 = lsmbuf[lr * NOUT + lane * 2 + 1];
            float mx = fmaxf(v0, v1);
#pragma unroll
            for (int o = 16; o; o >>= 1) mx = fmaxf(mx, __shfl_xor_sync(0xFFFFFFFFu, mx, o));
            float s = expf(v0 - mx) + expf(v1 - mx);
#pragma unroll
            for (int o = 16; o; o >>= 1) s += __shfl_xor_sync(0xFFFFFFFFu, s, o);
            float l = mx + logf(s);
            if (row < Nn)
                *(float2*)(outm + (size_t)row * NOUT + lane * 2) =
                    make_float2(v0 - l, v1 - l);
        }
    }
}

// ------------------------------- launcher ----------------------------------
extern "C" void kernel_launch(void* const* d_in, const int* in_sizes, int n_in,
                              void* d_out, int out_size) {
    const float* x    = (const float*)d_in[0];
    const int*   ei   = (const int*)d_in[1];
    const float* Wp   = (const float*)d_in[2];
    const float* bp   = (const float*)d_in[3];
    const float* Wl_h = (const float*)d_in[4];
    const float* bl_h = (const float*)d_in[5];
    const float* Wr_h = (const float*)d_in[6];
    const float* Wl_o = (const float*)d_in[7];
    const float* bl_o = (const float*)d_in[8];
    const float* Wr_o = (const float*)d_in[9];
    const int* src = ei;
    const int* dst = ei + Ee;
    float* out = (float*)d_out;

    float* p_inp;
    cudaGetSymbolAddress((void**)&p_inp, g_inp);
    __nv_bfloat16 *p_x, *p_h0, *p_h1, *p_m, *p_bw;
    cudaGetSymbolAddress((void**)&p_x, g_x);
    cudaGetSymbolAddress((void**)&p_h0, g_h0);
    cudaGetSymbolAddress((void**)&p_h1, g_h1);
    cudaGetSymbolAddress((void**)&p_m, g_m);
    cudaGetSymbolAddress((void**)&p_bw, g_Bw);

    auto gemm_in  = k_mgemm<128, 1, true, false, true, false, true, false>;
    auto gemm_hid = k_mgemm<128, 2, true, true, false, false, true, false>;
    auto gemm_out = k_mgemm<64, 2, false, false, false, false, false, true>;
    const int SM_IN  = 1 * 128 * 272 + 128 * 272 + 512;  // 70144
    const int SM_HID = 2 * 128 * 272 + 128 * 272 + 512;  // 104960
    const int SM_OUT = 2 * 128 * 272 + 64 * 272 + 256;   // 87296 (lsm buf 32KB reuses A)
    cudaFuncSetAttribute(gemm_in, cudaFuncAttributeMaxDynamicSharedMemorySize, SM_IN);
    cudaFuncSetAttribute(gemm_hid, cudaFuncAttributeMaxDynamicSharedMemorySize, SM_HID);
    cudaFuncSetAttribute(gemm_out, cudaFuncAttributeMaxDynamicSharedMemorySize, SM_OUT);

    // Launch order: ncu captures launch index 3 -> gemm_in.
    k_wconv<<<(WTOT + 255) / 256, 256>>>(Wp, Wl_h, Wr_h, Wl_o, Wr_o);          // 0
    k_xconv<<<(Nn * 32 + 255) / 256, 256>>>(x);                                // 1
    k_zero_cnt<<<(Nn + 255) / 256, 256>>>();                                   // 2
    gemm_in<<<NT, 512, SM_IN>>>(p_x, nullptr, p_bw + WOFF_IN,                  // 3
                                bp, nullptr, nullptr, p_inp, p_h0);
    k_hist<<<(Ee + 255) / 256, 256>>>(dst);                                    // 4
    k_scan<<<1, 1024>>>();                                                     // 5
    k_fill<<<(Ee + 255) / 256, 256>>>(src, dst);                               // 6

    const int ga = ((Nn * 32) + 255) / 256;

    __nv_bfloat16 *h = p_h0, *nh = p_h1;
    for (int i = 0; i < 3; i++) {
        k_agg<<<ga, 256>>>(h);
        gemm_hid<<<NT, 512, SM_HID>>>(p_m, h, p_bw + WOFF_H + i * 32768,
                                      bl_h + (size_t)i * 128, p_inp,
                                      nullptr, nullptr, nh);
        __nv_bfloat16* t = h; h = nh; nh = t;
    }

    k_agg<<<ga, 256>>>(h);
    gemm_out<<<NT, 512, SM_OUT>>>(p_m, h, p_bw + WOFF_O,
                                  bl_o, nullptr, out, nullptr, nullptr);
}

// round 17
// speedup vs baseline: 1.0786x; 1.0320x over previous
#include <cuda_runtime.h>
#include <cuda_bf16.h>
#include <cstdint>

// ---------------------------------------------------------------------------
// GraphSAGE forward on GB300 — bf16 everything (activations, weights,
// residual), 1-pass mma.sync GEMMs with fused x-conversion + log-softmax,
// 8-deep CSR mean aggregation.
// ---------------------------------------------------------------------------
namespace {
constexpr int Nn = 100000;   // nodes
constexpr int Ee = 1600000;  // edges
constexpr int Hc = 128;      // hidden channels
constexpr int Oc = 64;       // out channels
constexpr int NP = 100096;   // padded rows (multiple of 128)
constexpr int NT = NP / 128; // 782 CTA tiles
// weight scratch layout (combined [Wl|Wr] per layer, row-major [n][k])
constexpr int WOFF_IN = 0;
constexpr int WOFF_H = 16384;
constexpr int WOFF_O = 16384 + 3 * 32768;
constexpr int WTOT = WOFF_O + 64 * 256;  // 131072
}

// ------------------------- static device scratch ---------------------------
__device__ __align__(16) __nv_bfloat16 g_inp[(size_t)NP * Hc]; // pre-relu inProj
__device__ __align__(16) __nv_bfloat16 g_h0[(size_t)NP * Hc];  // h ping
__device__ __align__(16) __nv_bfloat16 g_h1[(size_t)NP * Hc];  // h pong
__device__ __align__(16) __nv_bfloat16 g_m[(size_t)NP * Hc];   // mean
__device__ float g_invdeg[Nn];
__device__ int   g_cnt[Nn];
__device__ int   g_rowptr[Nn + 1];
__device__ int   g_cursor[Nn];
__device__ int   g_csr[Ee];
__device__ __align__(16) __nv_bfloat16 g_Bw[WTOT];

// ------------------------------ PTX helpers --------------------------------
__device__ __forceinline__ uint32_t smem_to_u32(const void* p) {
    uint32_t a;
    asm("{ .reg .u64 t; cvta.to.shared.u64 t, %1; cvt.u32.u64 %0, t; }"
        : "=r"(a) : "l"(p));
    return a;
}
__device__ __forceinline__ void ldsm_x4(uint32_t* r, uint32_t addr) {
    asm volatile("ldmatrix.sync.aligned.m8n8.x4.shared.b16 {%0,%1,%2,%3}, [%4];"
                 : "=r"(r[0]), "=r"(r[1]), "=r"(r[2]), "=r"(r[3]) : "r"(addr));
}
__device__ __forceinline__ void mma_bf16(float* c, const uint32_t* a, const uint32_t* b) {
    asm volatile(
        "mma.sync.aligned.m16n8k16.row.col.f32.bf16.bf16.f32 "
        "{%0,%1,%2,%3}, {%4,%5,%6,%7}, {%8,%9}, {%0,%1,%2,%3};"
        : "+f"(c[0]), "+f"(c[1]), "+f"(c[2]), "+f"(c[3])
        : "r"(a[0]), "r"(a[1]), "r"(a[2]), "r"(a[3]), "r"(b[0]), "r"(b[1]));
}
__device__ __forceinline__ void cp16(uint32_t saddr, const void* g) {
    asm volatile("cp.async.cg.shared.global [%0], [%1], 16;"
                 :: "r"(saddr), "l"(g) : "memory");
}
#define CP_COMMIT() asm volatile("cp.async.commit_group;" ::: "memory")
#define CP_WAIT0()  asm volatile("cp.async.wait_group 0;" ::: "memory")

__device__ __forceinline__ uint32_t pack_bf2(float a, float b) {
    __nv_bfloat162 v = __floats2bfloat162_rn(a, b);
    return *reinterpret_cast<uint32_t*>(&v);
}
__device__ __forceinline__ float2 bf2_to_f2(uint32_t u) {
    __nv_bfloat162 b = *reinterpret_cast<__nv_bfloat162*>(&u);
    return __bfloat1622float2(b);
}

// ----------------------------- CSR construction ----------------------------
__global__ void k_zero_cnt() {
    int i = blockIdx.x * blockDim.x + threadIdx.x;
    if (i < Nn) g_cnt[i] = 0;
}
__global__ void k_hist(const int* __restrict__ dst) {
    int i = blockIdx.x * blockDim.x + threadIdx.x;
    if (i < Ee) atomicAdd(&g_cnt[dst[i]], 1);
}
__global__ void k_scan() {
    __shared__ int sums[1024];
    const int t = threadIdx.x;
    const int CH = 128;
    const int base = t * CH;
    int s = 0;
    for (int i = 0; i < CH; i++) {
        int idx = base + i;
        if (idx < Nn) s += g_cnt[idx];
    }
    sums[t] = s;
    __syncthreads();
    int mine = s;
    for (int d = 1; d < 1024; d <<= 1) {
        int v = (t >= d) ? sums[t - d] : 0;
        __syncthreads();
        sums[t] += v;
        __syncthreads();
    }
    int run = sums[t] - mine;
    for (int i = 0; i < CH; i++) {
        int idx = base + i;
        if (idx < Nn) {
            int c = g_cnt[idx];
            g_rowptr[idx] = run;
            g_cursor[idx] = run;
            g_invdeg[idx] = 1.0f / fmaxf((float)c, 1.0f);
            run += c;
        }
    }
    if (t == 0) g_rowptr[Nn] = Ee;
}
__global__ void k_fill(const int* __restrict__ src, const int* __restrict__ dst) {
    int i = blockIdx.x * blockDim.x + threadIdx.x;
    if (i < Ee) {
        int d = dst[i];
        int pos = atomicAdd(&g_cursor[d], 1);
        g_csr[pos] = src[i];
    }
}

// ------ mean aggregation (warp / node, contiguous bf16 rows, 256B/edge) ----
__global__ __launch_bounds__(256) void k_agg(const __nv_bfloat16* __restrict__ h) {
    int warp = (blockIdx.x * blockDim.x + threadIdx.x) >> 5;
    if (warp >= Nn) return;
    int lane = threadIdx.x & 31;
    const char* base = (const char*)h;
    const uint32_t loff = (uint32_t)(lane * 8);
    int b = g_rowptr[warp];
    int e = g_rowptr[warp + 1];
    float a0 = 0.f, a1 = 0.f, a2 = 0.f, a3 = 0.f;
    int i = b;
    for (; i + 7 < e; i += 8) {
        uint2 u[8];
#pragma unroll
        for (int j = 0; j < 8; j++)
            u[j] = *(const uint2*)(base + (size_t)g_csr[i + j] * 256 + loff);
#pragma unroll
        for (int j = 0; j < 8; j++) {
            float2 f;
            f = bf2_to_f2(u[j].x); a0 += f.x; a1 += f.y;
            f = bf2_to_f2(u[j].y); a2 += f.x; a3 += f.y;
        }
    }
    for (; i < e; i++) {
        uint2 u0 = *(const uint2*)(base + (size_t)g_csr[i] * 256 + loff);
        float2 f;
        f = bf2_to_f2(u0.x); a0 += f.x; a1 += f.y;
        f = bf2_to_f2(u0.y); a2 += f.x; a3 += f.y;
    }
    float id = g_invdeg[warp];
    a0 *= id; a1 *= id; a2 *= id; a3 *= id;
    *(uint2*)((char*)g_m + (size_t)warp * 256 + loff) =
        make_uint2(pack_bf2(a0, a1), pack_bf2(a2, a3));
}

// ------------------------ weight conversion ---------------------------------
__global__ void k_wconv(const float* __restrict__ Wp, const float* __restrict__ Wl_h,
                        const float* __restrict__ Wr_h, const float* __restrict__ Wl_o,
                        const float* __restrict__ Wr_o) {
    int i = blockIdx.x * blockDim.x + threadIdx.x;
    if (i >= WTOT) return;
    float w;
    if (i < WOFF_H) {
        w = Wp[i];
    } else if (i < WOFF_O) {
        int j = i - WOFF_H;
        int layer = j / 32768;
        int r = j % 32768;
        int n = r >> 8, k = r & 255;
        w = (k < 128) ? Wl_h[layer * 16384 + n * 128 + k]
                      : Wr_h[layer * 16384 + n * 128 + (k - 128)];
    } else {
        int r = i - WOFF_O;
        int n = r >> 8, k = r & 255;
        w = (k < 128) ? Wl_o[n * 128 + k] : Wr_o[n * 128 + (k - 128)];
    }
    g_Bw[i] = __float2bfloat16(w);
}

// --------------------- smem-fed mma.sync 1-pass GEMM -----------------------
// CTA m128 x nNOUT, 512 threads = 16 warps (8m x 2n), warp m16 x n(NOUT/2).
// A: bf16 activations staged via cp.async (pitch 272), or fp32 source
// converted in-flight when AF32. B: bf16 weights per phase. D = A*B.
// LSM: fused log-softmax over NOUT=64 columns, written to outm.
template <int NOUT, int NPH, bool RELU, bool RESID, bool PRE, bool WM, bool WPK,
          bool LSM, bool AF32>
__global__ __launch_bounds__(512) void k_mgemm(
    const void* __restrict__ A0v, const __nv_bfloat16* __restrict__ A1,
    const __nv_bfloat16* __restrict__ Bw,
    const float* __restrict__ bias, const __nv_bfloat16* __restrict__ resid,
    float* __restrict__ outm, __nv_bfloat16* __restrict__ outp,
    __nv_bfloat16* __restrict__ outb) {
    extern __shared__ char smem[];
    constexpr int ASZ = 128 * 272;           // A plane per phase (pitch 272B)
    constexpr int OFF_B = NPH * ASZ;
    constexpr int BPL = NOUT * 272;          // B plane (pitch 272B)
    constexpr int OFF_BIAS = OFF_B + BPL;
    constexpr int KTOT = NPH * 128;
    constexpr int NI = NOUT / 16;            // n8 tiles per warp (8 or 4)
    constexpr int NW = NI * 8;               // warp n width

    const uint32_t sm32 = smem_to_u32(smem);
    const int tid = threadIdx.x;
    const int lane = tid & 31;
    const int wid = tid >> 5;
    const int wm = wid & 7;                  // m block (16 rows)
    const int wn = wid >> 3;                 // n block (NW cols)
    const int m0 = blockIdx.x * 128;

    // ---- stage A phases (cp.async for bf16 planes) + B phase 0 ----
    if (!AF32) {
#pragma unroll
        for (int p = 0; p < NPH; p++) {
            const __nv_bfloat16* Ap =
                (p ? A1 : (const __nv_bfloat16*)A0v) + (size_t)m0 * 128;
            for (int idx = tid; idx < 2048; idx += 512) {
                int r = idx >> 4, g = idx & 15;
                cp16(sm32 + p * ASZ + r * 272 + g * 16, Ap + (size_t)r * 128 + g * 8);
            }
        }
    }
    for (int g = tid; g < NOUT * 16; g += 512) {
        int n = g >> 4, c = g & 15;
        cp16(sm32 + OFF_B + n * 272 + c * 16, Bw + (size_t)n * KTOT + c * 8);
    }
    CP_COMMIT();
    if (AF32) {
        // convert fp32 x rows -> bf16 smem in-flight (NPH == 1)
        const float* Ax = (const float*)A0v;
        for (int idx = tid; idx < 2048; idx += 512) {
            int r = idx >> 4, g = idx & 15;
            int grow = m0 + r;
            uint4 o = make_uint4(0u, 0u, 0u, 0u);
            if (grow < Nn) {
                const float4* s = (const float4*)(Ax + (size_t)grow * 128 + g * 8);
                float4 f0 = s[0], f1 = s[1];
                o = make_uint4(pack_bf2(f0.x, f0.y), pack_bf2(f0.z, f0.w),
                               pack_bf2(f1.x, f1.y), pack_bf2(f1.z, f1.w));
            }
            *(uint4*)(smem + r * 272 + g * 16) = o;
        }
    }
    if (tid < NOUT) *(float*)(smem + OFF_BIAS + tid * 4) = bias[tid];
    CP_WAIT0();
    __syncthreads();

    const int r8 = lane & 7, q = lane >> 3;
    const uint32_t aoff =
        (uint32_t)((wm * 16 + (q & 1) * 8 + r8) * 272 + (q >> 1) * 16);
    const uint32_t boff =
        (uint32_t)((wn * NW + (q >> 1) * 8 + r8) * 272 + (q & 1) * 16);
    const uint32_t bBase = sm32 + OFF_B + boff;

    float acc[NI][4];
#pragma unroll
    for (int ni = 0; ni < NI; ni++)
#pragma unroll
        for (int c = 0; c < 4; c++) acc[ni][c] = 0.f;

#pragma unroll
    for (int p = 0; p < NPH; p++) {
        if (p > 0) {
            __syncthreads();
            for (int g = tid; g < NOUT * 16; g += 512) {
                int n = g >> 4, c = g & 15;
                cp16(sm32 + OFF_B + n * 272 + c * 16,
                     Bw + (size_t)n * KTOT + p * 128 + c * 8);
            }
            CP_COMMIT();
            CP_WAIT0();
            __syncthreads();
        }
        const uint32_t aBase = sm32 + (uint32_t)(p * ASZ) + aoff;
#pragma unroll
        for (int kb = 0; kb < 8; kb++) {
            uint32_t a[4];
            ldsm_x4(a, aBase + kb * 32);
            uint32_t bf[NI / 2][4];
#pragma unroll
            for (int nt = 0; nt < NI / 2; nt++)
                ldsm_x4(bf[nt], bBase + nt * 16 * 272 + kb * 32);
#pragma unroll
            for (int ni = 0; ni < NI; ni++)
                mma_bf16(acc[ni], a, &bf[ni >> 1][(ni & 1) * 2]);
        }
    }

    if (LSM) __syncthreads();  // A smem no longer needed; reuse as fp32 buffer
    float* lsmbuf = (float*)smem;

    // ------------------------------ epilogue -------------------------------
    const float* biasS = (const float*)(smem + OFF_BIAS);
    const int q4 = lane & 3;
    const int rbase = m0 + wm * 16 + (lane >> 2);
#pragma unroll
    for (int ni = 0; ni < NI; ni++) {
        const int col = wn * NW + ni * 8 + q4 * 2;
        const float b0 = biasS[col], b1 = biasS[col + 1];
#pragma unroll
        for (int half = 0; half < 2; half++) {
            const int row = rbase + half * 8;
            float x0 = acc[ni][half * 2 + 0] + b0;
            float x1 = acc[ni][half * 2 + 1] + b1;
            if (PRE)
                *(uint32_t*)((char*)outp + (size_t)row * 256 + col * 2) = pack_bf2(x0, x1);
            if (RELU) { x0 = fmaxf(x0, 0.f); x1 = fmaxf(x1, 0.f); }
            if (RESID) {
                uint32_t ru =
                    *(const uint32_t*)((const char*)resid + (size_t)row * 256 + col * 2);
                float2 rr = bf2_to_f2(ru);
                x0 = fmaf(0.2f, rr.x, x0);
                x1 = fmaf(0.2f, rr.y, x1);
            }
            if (WM) {
                if (row < Nn)
                    *(float2*)(outm + (size_t)row * NOUT + col) = make_float2(x0, x1);
            }
            if (WPK)
                *(uint32_t*)((char*)outb + (size_t)row * 256 + col * 2) = pack_bf2(x0, x1);
            if (LSM) {
                lsmbuf[(row - m0) * NOUT + col] = x0;
                lsmbuf[(row - m0) * NOUT + col + 1] = x1;
            }
        }
    }

    if (LSM) {
        __syncthreads();
#pragma unroll
        for (int rr = 0; rr < 8; rr++) {
            const int lr = wid * 8 + rr;
            const int row = m0 + lr;
            float v0 = lsmbuf[lr * NOUT + lane * 2];
            float v1 = lsmbuf[lr * NOUT + lane * 2 + 1];
            float mx = fmaxf(v0, v1);
#pragma unroll
            for (int o = 16; o; o >>= 1) mx = fmaxf(mx, __shfl_xor_sync(0xFFFFFFFFu, mx, o));
            float s = expf(v0 - mx) + expf(v1 - mx);
#pragma unroll
            for (int o = 16; o; o >>= 1) s += __shfl_xor_sync(0xFFFFFFFFu, s, o);
            float l = mx + logf(s);
            if (row < Nn)
                *(float2*)(outm + (size_t)row * NOUT + lane * 2) =
                    make_float2(v0 - l, v1 - l);
        }
    }
}

// ------------------------------- launcher ----------------------------------
extern "C" void kernel_launch(void* const* d_in, const int* in_sizes, int n_in,
                              void* d_out, int out_size) {
    const float* x    = (const float*)d_in[0];
    const int*   ei   = (const int*)d_in[1];
    const float* Wp   = (const float*)d_in[2];
    const float* bp   = (const float*)d_in[3];
    const float* Wl_h = (const float*)d_in[4];
    const float* bl_h = (const float*)d_in[5];
    const float* Wr_h = (const float*)d_in[6];
    const float* Wl_o = (const float*)d_in[7];
    const float* bl_o = (const float*)d_in[8];
    const float* Wr_o = (const float*)d_in[9];
    const int* src = ei;
    const int* dst = ei + Ee;
    float* out = (float*)d_out;

    __nv_bfloat16 *p_inp, *p_h0, *p_h1, *p_m, *p_bw;
    cudaGetSymbolAddress((void**)&p_inp, g_inp);
    cudaGetSymbolAddress((void**)&p_h0, g_h0);
    cudaGetSymbolAddress((void**)&p_h1, g_h1);
    cudaGetSymbolAddress((void**)&p_m, g_m);
    cudaGetSymbolAddress((void**)&p_bw, g_Bw);

    auto gemm_in  = k_mgemm<128, 1, true, false, true, false, true, false, true>;
    auto gemm_hid = k_mgemm<128, 2, true, true, false, false, true, false, false>;
    auto gemm_out = k_mgemm<64, 2, false, false, false, false, false, true, false>;
    const int SM_IN  = 1 * 128 * 272 + 128 * 272 + 512;  // 70144
    const int SM_HID = 2 * 128 * 272 + 128 * 272 + 512;  // 104960
    const int SM_OUT = 2 * 128 * 272 + 64 * 272 + 256;   // 87296
    cudaFuncSetAttribute(gemm_in, cudaFuncAttributeMaxDynamicSharedMemorySize, SM_IN);
    cudaFuncSetAttribute(gemm_hid, cudaFuncAttributeMaxDynamicSharedMemorySize, SM_HID);
    cudaFuncSetAttribute(gemm_out, cudaFuncAttributeMaxDynamicSharedMemorySize, SM_OUT);

    // Launch order: ncu captures launch index 3 -> gemm_in.
    k_wconv<<<(WTOT + 255) / 256, 256>>>(Wp, Wl_h, Wr_h, Wl_o, Wr_o);          // 0
    k_zero_cnt<<<(Nn + 255) / 256, 256>>>();                                   // 1
    k_hist<<<(Ee + 255) / 256, 256>>>(dst);                                    // 2
    gemm_in<<<NT, 512, SM_IN>>>(x, nullptr, p_bw + WOFF_IN,                    // 3
                                bp, nullptr, nullptr, p_inp, p_h0);
    k_scan<<<1, 1024>>>();                                                     // 4
    k_fill<<<(Ee + 255) / 256, 256>>>(src, dst);                               // 5

    const int ga = ((Nn * 32) + 255) / 256;

    __nv_bfloat16 *h = p_h0, *nh = p_h1;
    for (int i = 0; i < 3; i++) {
        k_agg<<<ga, 256>>>(h);
        gemm_hid<<<NT, 512, SM_HID>>>(p_m, h, p_bw + WOFF_H + i * 32768,
                                      bl_h + (size_t)i * 128, p_inp,
                                      nullptr, nullptr, nh);
        __nv_bfloat16* t = h; h = nh; nh = t;
    }

    k_agg<<<ga, 256>>>(h);
    gemm_out<<<NT, 512, SM_OUT>>>(p_m, h, p_bw + WOFF_O,
                                  bl_o, nullptr, out, nullptr, nullptr);
}